// round 8
// baseline (speedup 1.0000x reference)
#include <cuda_runtime.h>
#include <math.h>

// Fixed problem shapes: N=8192 atoms, E=32768 edges (guarded for safety).
#define N_MAX   8192
#define E_MAX   32768
#define ROWCAP  32          // padded CSR row capacity (Poisson(4): P(deg>32) ~ 0)
#define NCELL   25
#define NCELL3  15625       // 25^3
#define CINV    0.3125f     // 1/3.2 ; cell 3.2 > max cutoff 3.168 + drift margin
#define CORG    40.0f
#define NBLK    148         // <= SM count (B300:148, GB300:152) -> all blocks co-resident
#define NTHR    256

// ---------------- device scratch (zero-init; counters restored each run) ----------
__device__ int    g_cursor[N_MAX];
__device__ int    g_csr[N_MAX * ROWCAP];    // phase A: edge ids; after sweep1: col values
__device__ float  g_viol[N_MAX];
__device__ float  g_rad8[N_MAX];
__device__ float  g_pA[N_MAX * 3];
__device__ float  g_pB[N_MAX * 3];
__device__ float  g_pos2[N_MAX * 3];
__device__ int    g_ccount[NCELL3];
__device__ int    g_ccur[NCELL3];
__device__ int    g_coff[NCELL3 + 1];
__device__ float4 g_catom[N_MAX];
__device__ int    g_cidx[N_MAX];
__device__ float  g_l1part[NBLK];
__device__ float  g_l2part[NBLK];
__device__ float  g_l3part[NBLK];
__device__ int    g_barc[8];                // spin-barrier counters
__device__ int    g_done;                   // last-block ticket

// ---------------- chemistry as branchy constants ----------------
__device__ __forceinline__ float maxval_of(int z) {
    switch (z) {
        case 6:  return 4.f; case 7:  return 3.f; case 8:  return 2.f;
        case 16: return 6.f; case 15: return 5.f;
        case 9: case 17: case 35: case 53: case 1: return 1.f;
        default: return 4.f;
    }
}
__device__ __forceinline__ float vdw_of(int z) {
    switch (z) {
        case 1:  return 1.2f;  case 6:  return 1.7f;  case 7:  return 1.55f;
        case 8:  return 1.52f; case 9:  return 1.47f; case 15: return 1.8f;
        case 16: return 1.8f;  case 17: return 1.75f; case 35: return 1.85f;
        case 53: return 1.98f; default: return 1.6f;
    }
}
__device__ __forceinline__ float bond_of(int a, int b) {
    if (a > b) { int t = a; a = b; b = t; }
    switch (a * 64 + b) {
        case 1*64+6:  return 1.09f; case 1*64+7:  return 1.01f; case 1*64+8:  return 0.96f;
        case 6*64+6:  return 1.54f; case 6*64+7:  return 1.47f; case 6*64+8:  return 1.43f;
        case 6*64+9:  return 1.35f; case 6*64+16: return 1.82f; case 6*64+17: return 1.77f;
        case 7*64+7:  return 1.45f; case 7*64+8:  return 1.40f; case 8*64+8:  return 1.48f;
        case 8*64+15: return 1.63f; case 16*64+16: return 2.05f;
        default: return 1.5f;
    }
}
__device__ __forceinline__ int cell_coord(float v) {
    int c = (int)floorf((v + CORG) * CINV);
    return min(max(c, 0), NCELL - 1);
}
__device__ __forceinline__ int cell_of(float x, float y, float z) {
    return (cell_coord(z) * NCELL + cell_coord(y)) * NCELL + cell_coord(x);
}

// ---------------- grid-wide spin barrier (all NBLK blocks resident) ----------------
__device__ __forceinline__ void gbar(int idx) {
    __syncthreads();
    if (threadIdx.x == 0) {
        __threadfence();
        atomicAdd(&g_barc[idx], 1);
        while (*(volatile int*)&g_barc[idx] < NBLK) { }
        __threadfence();
    }
    __syncthreads();
}

__device__ __forceinline__ float blockReduce(float v, float* sh) {
    int tid = threadIdx.x;
    sh[tid] = v;
    for (int d = NTHR / 2; d > 0; d >>= 1) {
        __syncthreads();
        if (tid < d) sh[tid] += sh[tid + d];
    }
    __syncthreads();
    float r = sh[0];
    __syncthreads();
    return r;
}

// ---------------- the megakernel: entire pipeline, one launch ----------------
__global__ void __launch_bounds__(NTHR) k_mega(
    const float* __restrict__ pos, const int* __restrict__ row,
    const int* __restrict__ col, const int* __restrict__ types,
    float* __restrict__ out, int N, int E, int out_size)
{
    __shared__ float sh[NTHR];
    __shared__ int   shi[NTHR];
    __shared__ int   amLast;
    const int tid  = threadIdx.x;
    const int gtid = blockIdx.x * NTHR + tid;
    const int GT   = NBLK * NTHR;

    // ---- Phase A: build padded CSR of edge ids ----
    for (int e = gtid; e < E; e += GT) {
        int r = row[e];
        int p = atomicAdd(&g_cursor[r], 1);
        if (p < ROWCAP) g_csr[r * ROWCAP + p] = e;
    }
    gbar(0);

    // ---- Phase B: sweep 1 (sort rows -> original edge order, viol/loss1/rad8, push) ----
    {
        float lloss = 0.0f;
        for (int i = gtid; i < N; i += GT) {
            int deg = g_cursor[i];
            int cnt = min(deg, ROWCAP);
            int z = types[i];
            float v = fmaxf((float)deg - maxval_of(z), 0.0f);
            g_viol[i] = v;
            lloss += v * v;
            g_rad8[i] = vdw_of(z) * 0.8f;
            float x = pos[3*i], y = pos[3*i+1], zz = pos[3*i+2];
            if (v > 0.0f) {
                int eid[ROWCAP];
                for (int k = 0; k < cnt; k++) eid[k] = g_csr[i * ROWCAP + k];
                for (int a = 1; a < cnt; a++) {          // stable order = ascending edge id
                    int key = eid[a]; int t = a - 1;
                    while (t >= 0 && eid[t] > key) { eid[t+1] = eid[t]; t--; }
                    eid[t+1] = key;
                }
                int cc[ROWCAP];
                for (int k = 0; k < cnt; k++) { cc[k] = col[eid[k]]; g_csr[i*ROWCAP+k] = cc[k]; }
                float nx[ROWCAP], ny[ROWCAP], nz[ROWCAP];
                for (int k = 0; k < cnt; k++) {
                    int c = cc[k];
                    nx[k] = pos[3*c]; ny[k] = pos[3*c+1]; nz[k] = pos[3*c+2];
                }
                float s = v * 1e-3f;
                for (int k = 0; k < cnt; k++) {
                    if (cc[k] == i) continue;            // self-edge contributes exactly 0
                    float dx = x - nx[k], dy = y - ny[k], dz = zz - nz[k];
                    float d2 = dx*dx + dy*dy + dz*dz;
                    float f = s * rsqrtf(fmaxf(d2, 1e-24f));
                    x += dx * f; y += dy * f; zz += dz * f;
                }
            }
            g_pA[3*i] = x; g_pA[3*i+1] = y; g_pA[3*i+2] = zz;
        }
        float t = blockReduce(lloss, sh);
        if (tid == 0) g_l1part[blockIdx.x] = t;
    }
    gbar(1);

    // ---- Phases C,D: sweeps 2,3 (rows < i read previous sweep via L2) ----
    for (int sweep = 0; sweep < 2; sweep++) {
        const float* prev = (sweep == 0) ? g_pA : g_pB;
        float* outp       = (sweep == 0) ? g_pB : g_pA;
        for (int i = gtid; i < N; i += GT) {
            float x = pos[3*i], y = pos[3*i+1], zz = pos[3*i+2];
            float v = g_viol[i];
            if (v > 0.0f) {
                int cnt = min(g_cursor[i], ROWCAP);
                int cc[ROWCAP];
                for (int k = 0; k < cnt; k++) cc[k] = g_csr[i * ROWCAP + k];
                float nx[ROWCAP], ny[ROWCAP], nz[ROWCAP];
                for (int k = 0; k < cnt; k++) {
                    int c = cc[k];
                    if (c < i) {    // cross-block data -> L2 (L1 may be stale)
                        nx[k] = __ldcg(&prev[3*c]);
                        ny[k] = __ldcg(&prev[3*c+1]);
                        nz[k] = __ldcg(&prev[3*c+2]);
                    } else {
                        nx[k] = pos[3*c]; ny[k] = pos[3*c+1]; nz[k] = pos[3*c+2];
                    }
                }
                float s = v * 1e-3f;
                for (int k = 0; k < cnt; k++) {
                    if (cc[k] == i) continue;
                    float dx = x - nx[k], dy = y - ny[k], dz = zz - nz[k];
                    float d2 = dx*dx + dy*dy + dz*dz;
                    float f = s * rsqrtf(fmaxf(d2, 1e-24f));
                    x += dx * f; y += dy * f; zz += dz * f;
                }
            }
            outp[3*i] = x; outp[3*i+1] = y; outp[3*i+2] = zz;
            if (sweep == 1) { g_pos2[3*i] = x; g_pos2[3*i+1] = y; g_pos2[3*i+2] = zz; }
        }
        gbar(2 + sweep);
    }

    // ---- Phase E: bond correction (atomics into pos2) + cell counts (on pA) ----
    {
        float l2 = 0.0f;
        for (int e = gtid; e < E; e += GT) {
            int r = row[e], c = col[e];
            float dx = __ldcg(&g_pA[3*r])   - __ldcg(&g_pA[3*c]);
            float dy = __ldcg(&g_pA[3*r+1]) - __ldcg(&g_pA[3*c+1]);
            float dz = __ldcg(&g_pA[3*r+2]) - __ldcg(&g_pA[3*c+2]);
            float cur = sqrtf(dx*dx + dy*dy + dz*dz);
            float tgt = bond_of(types[r], types[c]);
            float df = cur - tgt;
            l2 += df * df;
            float ratio = fminf(fmaxf(tgt / (cur + 1e-8f), 0.98f), 1.02f);
            float sc = (ratio - 1.0f) * 0.005f;     // *0.01*0.5
            atomicAdd(&g_pos2[3*r],     dx * sc);
            atomicAdd(&g_pos2[3*r+1],   dy * sc);
            atomicAdd(&g_pos2[3*r+2],   dz * sc);
            atomicAdd(&g_pos2[3*c],    -dx * sc);
            atomicAdd(&g_pos2[3*c+1],  -dy * sc);
            atomicAdd(&g_pos2[3*c+2],  -dz * sc);
        }
        for (int i = gtid; i < N; i += GT) {
            int c = cell_of(__ldcg(&g_pA[3*i]), __ldcg(&g_pA[3*i+1]), __ldcg(&g_pA[3*i+2]));
            atomicAdd(&g_ccount[c], 1);
        }
        float t = blockReduce(l2, sh);
        if (tid == 0) g_l2part[blockIdx.x] = t;
    }
    gbar(4);

    // ---- Phase F: exclusive scan of cell counts (block 0 only) ----
    if (blockIdx.x == 0) {
        const int NI = (NCELL3 + NTHR - 1) / NTHR;   // 62
        int s = 0;
        for (int k = 0; k < NI; k++) {
            int idx = tid * NI + k;
            if (idx < NCELL3) s += g_ccount[idx];
        }
        shi[tid] = s;
        __syncthreads();
        for (int d = 1; d < NTHR; d <<= 1) {
            int v2 = (tid >= d) ? shi[tid - d] : 0;
            __syncthreads();
            shi[tid] += v2;
            __syncthreads();
        }
        int run = shi[tid] - s;
        for (int k = 0; k < NI; k++) {
            int idx = tid * NI + k;
            if (idx < NCELL3) { g_coff[idx] = run; run += g_ccount[idx]; }
        }
        if (tid == 0) g_coff[NCELL3] = shi[NTHR - 1];
    }
    gbar(5);

    // ---- Phase G: fill cell CSR with pos2 packed ----
    for (int i = gtid; i < N; i += GT) {
        float ax = __ldcg(&g_pA[3*i]), ay = __ldcg(&g_pA[3*i+1]), az = __ldcg(&g_pA[3*i+2]);
        int c = cell_of(ax, ay, az);                 // identical binning to count phase
        int p = atomicAdd(&g_ccur[c], 1);
        int slot = __ldcg(&g_coff[c]) + p;
        g_catom[slot] = make_float4(__ldcg(&g_pos2[3*i]), __ldcg(&g_pos2[3*i+1]),
                                    __ldcg(&g_pos2[3*i+2]), g_rad8[i]);
        g_cidx[slot] = i;
    }
    gbar(6);

    // ---- Phase H: steric, warp-per-slot over 9 contiguous x-ranges ----
    {
        int wid = tid >> 5, lane = tid & 31;
        float l3 = 0.0f;
        for (int s = blockIdx.x * (NTHR / 32) + wid; s < N; s += NBLK * (NTHR / 32)) {
            float4 me = __ldcg(&g_catom[s]);
            int i = __ldcg(&g_cidx[s]);
            int cx = cell_coord(me.x), cy = cell_coord(me.y), cz = cell_coord(me.z);
            int xlo = max(cx - 1, 0), xhi = min(cx + 1, NCELL - 1);
            int ylo = max(cy - 1, 0), yhi = min(cy + 1, NCELL - 1);
            int zlo = max(cz - 1, 0), zhi = min(cz + 1, NCELL - 1);
            float csum = 0.0f, cvx = 0.0f, cvy = 0.0f, cvz = 0.0f;
            for (int z = zlo; z <= zhi; z++)
                for (int y = ylo; y <= yhi; y++) {
                    int rowc = (z * NCELL + y) * NCELL;
                    int kb = __ldcg(&g_coff[rowc + xlo]);
                    int ke = __ldcg(&g_coff[rowc + xhi + 1]);
                    for (int k = kb + lane; k < ke; k += 32) {
                        float4 q = __ldcg(&g_catom[k]);
                        if (k == s) continue;                     // exactly the diagonal
                        float dx = me.x - q.x, dy = me.y - q.y, dz = me.z - q.z;
                        float d2 = dx*dx + dy*dy + dz*dz;
                        float mind = me.w + q.w;
                        if (d2 < mind * mind) {
                            float d2c = fmaxf(d2, 1e-20f);
                            float inv = rsqrtf(d2c);
                            float dist = d2c * inv;
                            float tt = mind - dist;
                            if (tt > 0.0f) {
                                l3 += tt * tt;
                                if (dist > 1e-8f) {
                                    float cc = tt * 0.0025f * inv;
                                    csum += cc;
                                    cvx += cc * q.x; cvy += cc * q.y; cvz += cc * q.z;
                                }
                            }
                        }
                    }
                }
            #pragma unroll
            for (int d = 16; d > 0; d >>= 1) {
                csum += __shfl_xor_sync(0xffffffff, csum, d);
                cvx  += __shfl_xor_sync(0xffffffff, cvx,  d);
                cvy  += __shfl_xor_sync(0xffffffff, cvy,  d);
                cvz  += __shfl_xor_sync(0xffffffff, cvz,  d);
            }
            if (lane == 0) {
                out[3*i]   = me.x + csum * me.x - cvx;
                out[3*i+1] = me.y + csum * me.y - cvy;
                out[3*i+2] = me.z + csum * me.z - cvz;
            }
        }
        // restore zeroed counters for the next graph replay (last users were phases D/F/G)
        for (int k = gtid; k < N_MAX;  k += GT) g_cursor[k] = 0;
        for (int k = gtid; k < NCELL3; k += GT) { g_ccount[k] = 0; g_ccur[k] = 0; }
        float t = blockReduce(l3, sh);
        if (tid == 0) {
            g_l3part[blockIdx.x] = t;
            __threadfence();
            amLast = (atomicAdd(&g_done, 1) == NBLK - 1);
        }
        __syncthreads();
    }

    // ---- Phase I: last block finalizes loss + resets barrier state ----
    if (amLast) {
        float a1 = 0.0f, a2 = 0.0f, a3 = 0.0f;
        for (int k = tid; k < NBLK; k += NTHR) {
            a1 += __ldcg(&g_l1part[k]);
            a2 += __ldcg(&g_l2part[k]);
            a3 += __ldcg(&g_l3part[k]);
        }
        float s1 = blockReduce(a1, sh);
        float s2 = blockReduce(a2, sh);
        float s3 = blockReduce(a3, sh);
        if (tid == 0) out[3*N] = (s1 + s2 / (float)E + 0.5f * s3) * 0.1f;
        for (int k = 3*N + 1 + tid; k < out_size; k += NTHR) out[k] = 0.0f;
        if (tid < 8) g_barc[tid] = 0;
        if (tid == 0) g_done = 0;
    }
}

// ---------------- launcher: ONE kernel ----------------
extern "C" void kernel_launch(void* const* d_in, const int* in_sizes, int n_in,
                              void* d_out, int out_size) {
    const float* pos   = (const float*)d_in[0];
    const int*   edge  = (const int*)d_in[1];
    const int*   types = (const int*)d_in[2];
    float*       out   = (float*)d_out;

    int N = in_sizes[0] / 3;
    int E = in_sizes[1] / 2;
    const int* row = edge;
    const int* col = edge + E;

    k_mega<<<NBLK, NTHR>>>(pos, row, col, types, out, N, E, out_size);
}

// round 13
// speedup vs baseline: 1.2396x; 1.2396x over previous
#include <cuda_runtime.h>
#include <math.h>

// Fixed problem shapes: N=8192 atoms, E=32768 edges (guarded for safety).
#define N_MAX   8192
#define E_MAX   32768
#define ROWCAP  32          // padded CSR row capacity (Poisson(4): P(deg>32) ~ 0)
#define NCELL   25
#define NCELL3  15625       // 25^3
#define CINV    0.3125f     // 1/3.2 ; cell 3.2 > max cutoff 3.168 + drift margin
#define CORG    40.0f
#define NBLK    148         // <= SM count -> all blocks co-resident (1 block/SM)
#define NTHR    512
#define APB     56          // atoms per block  (148*56  = 8288  >= 8192)
#define EPB     222         // edges per block  (148*222 = 32856 >= 32768)
#define SPIN_LIMIT 200000000u   // bounded spin: converts any deadlock into fast wrong-result

// ---------------- device scratch (zero-init; counters restored each run) ----------
__device__ int    g_cursor[N_MAX];
__device__ int    g_csr[N_MAX * ROWCAP];    // phase A: edge ids; after sweep1: col values
__device__ float  g_viol[N_MAX];
__device__ float  g_rad8[N_MAX];
__device__ float  g_pA[N_MAX * 3];
__device__ float  g_pB[N_MAX * 3];
__device__ float  g_pos2[N_MAX * 3];
__device__ int    g_ccount[NCELL3];
__device__ int    g_ccur[NCELL3];
__device__ int    g_coff[NCELL3 + 1];
__device__ float4 g_catom[N_MAX];
__device__ int    g_cidx[N_MAX];
__device__ float  g_l1part[NBLK];
__device__ float  g_l2part[NBLK];
__device__ float  g_l3part[NBLK];
__device__ int    g_barc[8];
__device__ int    g_done;

// ---------------- chemistry as branchy constants ----------------
__device__ __forceinline__ float maxval_of(int z) {
    switch (z) {
        case 6:  return 4.f; case 7:  return 3.f; case 8:  return 2.f;
        case 16: return 6.f; case 15: return 5.f;
        case 9: case 17: case 35: case 53: case 1: return 1.f;
        default: return 4.f;
    }
}
__device__ __forceinline__ float vdw_of(int z) {
    switch (z) {
        case 1:  return 1.2f;  case 6:  return 1.7f;  case 7:  return 1.55f;
        case 8:  return 1.52f; case 9:  return 1.47f; case 15: return 1.8f;
        case 16: return 1.8f;  case 17: return 1.75f; case 35: return 1.85f;
        case 53: return 1.98f; default: return 1.6f;
    }
}
__device__ __forceinline__ float bond_of(int a, int b) {
    if (a > b) { int t = a; a = b; b = t; }
    switch (a * 64 + b) {
        case 1*64+6:  return 1.09f; case 1*64+7:  return 1.01f; case 1*64+8:  return 0.96f;
        case 6*64+6:  return 1.54f; case 6*64+7:  return 1.47f; case 6*64+8:  return 1.43f;
        case 6*64+9:  return 1.35f; case 6*64+16: return 1.82f; case 6*64+17: return 1.77f;
        case 7*64+7:  return 1.45f; case 7*64+8:  return 1.40f; case 8*64+8:  return 1.48f;
        case 8*64+15: return 1.63f; case 16*64+16: return 2.05f;
        default: return 1.5f;
    }
}
__device__ __forceinline__ int cell_coord(float v) {
    int c = (int)floorf((v + CORG) * CINV);
    return min(max(c, 0), NCELL - 1);
}
__device__ __forceinline__ int cell_of(float x, float y, float z) {
    return (cell_coord(z) * NCELL + cell_coord(y)) * NCELL + cell_coord(x);
}

// ------- grid-wide spin barrier (all NBLK blocks resident), BOUNDED wait ----------
// Normal release takes <1e6 polls; the 2e8 bound only trips on a true deadlock,
// turning a container-killing hang into a fast, diagnosable wrong-result run.
__device__ __forceinline__ void gbar(int idx) {
    __syncthreads();
    if (threadIdx.x == 0) {
        __threadfence();
        atomicAdd(&g_barc[idx], 1);
        unsigned spins = 0;
        while (*(volatile int*)&g_barc[idx] < NBLK) {
            if (++spins > SPIN_LIMIT) break;     // fail-open diagnostic, never trips normally
            __nanosleep(32);
        }
        __threadfence();
    }
    __syncthreads();
}

__device__ __forceinline__ float blockReduce(float v, float* sh) {
    int tid = threadIdx.x;
    sh[tid] = v;
    for (int d = NTHR / 2; d > 0; d >>= 1) {
        __syncthreads();
        if (tid < d) sh[tid] += sh[tid + d];
    }
    __syncthreads();
    float r = sh[0];
    __syncthreads();
    return r;
}

// ---------------- the megakernel: entire pipeline, one launch ----------------
__global__ void __launch_bounds__(NTHR) k_mega(
    const float* __restrict__ pos, const int* __restrict__ row,
    const int* __restrict__ col, const int* __restrict__ types,
    float* __restrict__ out, int N, int E, int out_size)
{
    __shared__ float sh[NTHR];
    __shared__ int   shi[NTHR];
    __shared__ int   amLast;
    const int tid = threadIdx.x;
    const int bid = blockIdx.x;
    // blocked per-phase ownership: this block's atom / edge ranges
    const int myAtom = (tid < APB) ? (bid * APB + tid) : N;     // >=N means inactive
    const int myEdge = (tid < EPB) ? (bid * EPB + tid) : E;

    // ---- Phase A: build padded CSR of edge ids (all 148 SMs) ----
    if (myEdge < E) {
        int r = row[myEdge];
        int p = atomicAdd(&g_cursor[r], 1);
        if (p < ROWCAP) g_csr[r * ROWCAP + p] = myEdge;
    }
    gbar(0);

    // ---- Phase B: sweep 1 (sort row -> original edge order, viol/loss1/rad8, push) ----
    {
        float lloss = 0.0f;
        int i = myAtom;
        if (i < N) {
            int deg = __ldcg(&g_cursor[i]);      // filled by atomics (L2) from other blocks
            int cnt = min(deg, ROWCAP);
            int z = types[i];
            float v = fmaxf((float)deg - maxval_of(z), 0.0f);
            g_viol[i] = v;
            lloss = v * v;
            g_rad8[i] = vdw_of(z) * 0.8f;
            float x = pos[3*i], y = pos[3*i+1], zz = pos[3*i+2];
            if (v > 0.0f) {
                int eid[ROWCAP];
                for (int k = 0; k < cnt; k++) eid[k] = __ldcg(&g_csr[i * ROWCAP + k]);
                for (int a = 1; a < cnt; a++) {  // stable order = ascending edge id
                    int key = eid[a]; int t = a - 1;
                    while (t >= 0 && eid[t] > key) { eid[t+1] = eid[t]; t--; }
                    eid[t+1] = key;
                }
                int cc[ROWCAP];
                for (int k = 0; k < cnt; k++) { cc[k] = col[eid[k]]; g_csr[i*ROWCAP+k] = cc[k]; }
                float s = v * 1e-3f;
                for (int k = 0; k < cnt; k++) {
                    int c = cc[k];
                    if (c == i) continue;        // self-edge contributes exactly 0
                    float dx = x - pos[3*c], dy = y - pos[3*c+1], dz = zz - pos[3*c+2];
                    float d2 = dx*dx + dy*dy + dz*dz;
                    float f = s * rsqrtf(fmaxf(d2, 1e-24f));
                    x += dx * f; y += dy * f; zz += dz * f;
                }
            }
            g_pA[3*i] = x; g_pA[3*i+1] = y; g_pA[3*i+2] = zz;
        }
        float t = blockReduce(lloss, sh);
        if (tid == 0) g_l1part[bid] = t;
    }
    gbar(1);

    // ---- Phases C,D: sweeps 2,3 (rows < i read previous sweep via L2) ----
    #pragma unroll 1
    for (int sweep = 0; sweep < 2; sweep++) {
        const float* prev = (sweep == 0) ? g_pA : g_pB;
        float* outp       = (sweep == 0) ? g_pB : g_pA;
        int i = myAtom;
        if (i < N) {
            float x = pos[3*i], y = pos[3*i+1], zz = pos[3*i+2];
            float v = g_viol[i];                 // own block wrote it -> L1 safe
            if (v > 0.0f) {
                int cnt = min(__ldcg(&g_cursor[i]), ROWCAP);
                float s = v * 1e-3f;
                for (int k0 = 0; k0 < cnt; k0 += 8) {
                    int m = min(cnt - k0, 8);
                    float nx[8], ny[8], nz[8]; int sk[8];
                    #pragma unroll
                    for (int t = 0; t < 8; t++) {
                        if (t < m) {
                            int c = g_csr[i * ROWCAP + k0 + t];  // own block wrote -> L1 safe
                            sk[t] = (c == i);
                            if (c < i) {          // cross-block result -> L2
                                nx[t] = __ldcg(&prev[3*c]);
                                ny[t] = __ldcg(&prev[3*c+1]);
                                nz[t] = __ldcg(&prev[3*c+2]);
                            } else {
                                nx[t] = pos[3*c]; ny[t] = pos[3*c+1]; nz[t] = pos[3*c+2];
                            }
                        } else sk[t] = 1;
                    }
                    #pragma unroll
                    for (int t = 0; t < 8; t++) {
                        if (!sk[t]) {
                            float dx = x - nx[t], dy = y - ny[t], dz = zz - nz[t];
                            float d2 = dx*dx + dy*dy + dz*dz;
                            float f = s * rsqrtf(fmaxf(d2, 1e-24f));
                            x += dx * f; y += dy * f; zz += dz * f;
                        }
                    }
                }
            }
            outp[3*i] = x; outp[3*i+1] = y; outp[3*i+2] = zz;
            if (sweep == 1) { g_pos2[3*i] = x; g_pos2[3*i+1] = y; g_pos2[3*i+2] = zz; }
        }
        gbar(2 + sweep);
    }

    // ---- Phase E: bond correction (atomics into pos2) + cell counts (on pA) ----
    {
        float l2 = 0.0f;
        int e = myEdge;
        if (e < E) {
            int r = row[e], c = col[e];
            float dx = __ldcg(&g_pA[3*r])   - __ldcg(&g_pA[3*c]);
            float dy = __ldcg(&g_pA[3*r+1]) - __ldcg(&g_pA[3*c+1]);
            float dz = __ldcg(&g_pA[3*r+2]) - __ldcg(&g_pA[3*c+2]);
            float cur = sqrtf(dx*dx + dy*dy + dz*dz);
            float tgt = bond_of(types[r], types[c]);
            float df = cur - tgt;
            l2 = df * df;
            float ratio = fminf(fmaxf(tgt / (cur + 1e-8f), 0.98f), 1.02f);
            float sc = (ratio - 1.0f) * 0.005f;     // *0.01*0.5
            atomicAdd(&g_pos2[3*r],     dx * sc);
            atomicAdd(&g_pos2[3*r+1],   dy * sc);
            atomicAdd(&g_pos2[3*r+2],   dz * sc);
            atomicAdd(&g_pos2[3*c],    -dx * sc);
            atomicAdd(&g_pos2[3*c+1],  -dy * sc);
            atomicAdd(&g_pos2[3*c+2],  -dz * sc);
        }
        int i = myAtom;
        if (i < N) {
            int c = cell_of(g_pA[3*i], g_pA[3*i+1], g_pA[3*i+2]);  // own block wrote pA[i]
            atomicAdd(&g_ccount[c], 1);
        }
        float t = blockReduce(l2, sh);
        if (tid == 0) g_l2part[bid] = t;
    }
    gbar(4);

    // ---- Phase F: exclusive scan of cell counts (block 0 only) ----
    if (bid == 0) {
        const int NI = (NCELL3 + NTHR - 1) / NTHR;   // 31
        int s = 0;
        for (int k = 0; k < NI; k++) {
            int idx = tid * NI + k;
            if (idx < NCELL3) s += __ldcg(&g_ccount[idx]);
        }
        shi[tid] = s;
        __syncthreads();
        for (int d = 1; d < NTHR; d <<= 1) {
            int v2 = (tid >= d) ? shi[tid - d] : 0;
            __syncthreads();
            shi[tid] += v2;
            __syncthreads();
        }
        int run = shi[tid] - s;
        for (int k = 0; k < NI; k++) {
            int idx = tid * NI + k;
            if (idx < NCELL3) { g_coff[idx] = run; run += __ldcg(&g_ccount[idx]); }
        }
        if (tid == 0) g_coff[NCELL3] = shi[NTHR - 1];
    }
    gbar(5);

    // ---- Phase G: fill cell CSR with pos2 packed ----
    {
        int i = myAtom;
        if (i < N) {
            int c = cell_of(g_pA[3*i], g_pA[3*i+1], g_pA[3*i+2]);  // identical binning
            int p = atomicAdd(&g_ccur[c], 1);
            int slot = __ldcg(&g_coff[c]) + p;
            g_catom[slot] = make_float4(__ldcg(&g_pos2[3*i]), __ldcg(&g_pos2[3*i+1]),
                                        __ldcg(&g_pos2[3*i+2]), g_rad8[i]);
            g_cidx[slot] = i;
        }
    }
    gbar(6);

    // ---- Phase H: steric, warp-per-slot over 9 contiguous x-ranges ----
    {
        int wid = tid >> 5, lane = tid & 31;
        const int WPB = NTHR / 32;                   // 16 warps/block
        float l3 = 0.0f;
        for (int s = bid * WPB + wid; s < N; s += NBLK * WPB) {
            float4 me = __ldcg(&g_catom[s]);
            int i = __ldcg(&g_cidx[s]);
            int cx = cell_coord(me.x), cy = cell_coord(me.y), cz = cell_coord(me.z);
            int xlo = max(cx - 1, 0), xhi = min(cx + 1, NCELL - 1);
            int ylo = max(cy - 1, 0), yhi = min(cy + 1, NCELL - 1);
            int zlo = max(cz - 1, 0), zhi = min(cz + 1, NCELL - 1);
            float csum = 0.0f, cvx = 0.0f, cvy = 0.0f, cvz = 0.0f;
            for (int z = zlo; z <= zhi; z++)
                for (int y = ylo; y <= yhi; y++) {
                    int rowc = (z * NCELL + y) * NCELL;
                    int kb = __ldcg(&g_coff[rowc + xlo]);
                    int ke = __ldcg(&g_coff[rowc + xhi + 1]);
                    for (int k = kb + lane; k < ke; k += 32) {
                        float4 q = __ldcg(&g_catom[k]);
                        if (k == s) continue;                 // exactly the diagonal
                        float dx = me.x - q.x, dy = me.y - q.y, dz = me.z - q.z;
                        float d2 = dx*dx + dy*dy + dz*dz;
                        float mind = me.w + q.w;
                        if (d2 < mind * mind) {
                            float d2c = fmaxf(d2, 1e-20f);
                            float inv = rsqrtf(d2c);
                            float dist = d2c * inv;
                            float tt = mind - dist;
                            if (tt > 0.0f) {
                                l3 += tt * tt;
                                if (dist > 1e-8f) {
                                    float cc = tt * 0.0025f * inv;
                                    csum += cc;
                                    cvx += cc * q.x; cvy += cc * q.y; cvz += cc * q.z;
                                }
                            }
                        }
                    }
                }
            #pragma unroll
            for (int d = 16; d > 0; d >>= 1) {
                csum += __shfl_xor_sync(0xffffffff, csum, d);
                cvx  += __shfl_xor_sync(0xffffffff, cvx,  d);
                cvy  += __shfl_xor_sync(0xffffffff, cvy,  d);
                cvz  += __shfl_xor_sync(0xffffffff, cvz,  d);
            }
            if (lane == 0) {
                out[3*i]   = me.x + csum * me.x - cvx;
                out[3*i+1] = me.y + csum * me.y - cvy;
                out[3*i+2] = me.z + csum * me.z - cvz;
            }
        }
        // restore zeroed counters for the next graph replay
        const int GT = NBLK * NTHR;
        const int gtid = bid * NTHR + tid;
        for (int k = gtid; k < N_MAX;  k += GT) g_cursor[k] = 0;
        for (int k = gtid; k < NCELL3; k += GT) { g_ccount[k] = 0; g_ccur[k] = 0; }
        float t = blockReduce(l3, sh);
        if (tid == 0) {
            g_l3part[bid] = t;
            __threadfence();
            amLast = (atomicAdd(&g_done, 1) == NBLK - 1);
        }
        __syncthreads();
    }

    // ---- Phase I: last block finalizes loss + resets barrier state ----
    if (amLast) {
        float a1 = 0.0f, a2 = 0.0f, a3 = 0.0f;
        for (int k = tid; k < NBLK; k += NTHR) {
            a1 += __ldcg(&g_l1part[k]);
            a2 += __ldcg(&g_l2part[k]);
            a3 += __ldcg(&g_l3part[k]);
        }
        float s1 = blockReduce(a1, sh);
        float s2 = blockReduce(a2, sh);
        float s3 = blockReduce(a3, sh);
        if (tid == 0) out[3*N] = (s1 + s2 / (float)E + 0.5f * s3) * 0.1f;
        for (int k = 3*N + 1 + tid; k < out_size; k += NTHR) out[k] = 0.0f;
        if (tid < 8) g_barc[tid] = 0;
        if (tid == 0) g_done = 0;
    }
}

// ---------------- launcher: ONE kernel ----------------
extern "C" void kernel_launch(void* const* d_in, const int* in_sizes, int n_in,
                              void* d_out, int out_size) {
    const float* pos   = (const float*)d_in[0];
    const int*   edge  = (const int*)d_in[1];
    const int*   types = (const int*)d_in[2];
    float*       out   = (float*)d_out;

    int N = in_sizes[0] / 3;
    int E = in_sizes[1] / 2;
    const int* row = edge;
    const int* col = edge + E;

    k_mega<<<NBLK, NTHR>>>(pos, row, col, types, out, N, E, out_size);
}

// round 14
// speedup vs baseline: 1.6275x; 1.3129x over previous
#include <cuda_runtime.h>
#include <math.h>

// Fixed problem shapes: N=8192 atoms, E=32768 edges (guarded for safety).
#define N_MAX   8192
#define E_MAX   32768
#define ROWCAP  32          // padded CSR row capacity (Poisson(4): P(deg>32) ~ 0)
#define NCELL   25
#define NCELL3  15625       // 25^3
#define CINV    0.3125f     // 1/3.2 ; cell 3.2 > max cutoff 3.168 + drift margin
#define CORG    40.0f

// ---------------- device scratch (zero-init; counters restored each run) ----------
__device__ int    g_cursor[N_MAX];          // per-row degree (atomic)
__device__ int    g_csr[N_MAX * ROWCAP];    // edge ids; after sweep1 (violating rows): col values
__device__ float  g_viol[N_MAX];
__device__ float  g_rad8[N_MAX];            // 0.8 * vdw radius
__device__ float  g_pA[N_MAX * 3];          // sweep ping
__device__ float  g_pB[N_MAX * 3];          // sweep pong
__device__ float  g_pos2[N_MAX * 3];        // after bond correction (float atomics)
__device__ int    g_ccount[NCELL3];
__device__ int    g_ccur[NCELL3];
__device__ int    g_coff[NCELL3 + 1];
__device__ float4 g_catom[N_MAX];           // cell-ordered (x,y,z,rad8) at pos2
__device__ int    g_cidx[N_MAX];            // cell-ordered original atom index
__device__ float  g_l1part[128];
__device__ float  g_l2part[128];
__device__ float  g_l3part[1024];
__device__ int    g_done;                   // last-block ticket for fused finalize

// ---------------- chemistry as branchy constants ----------------
__device__ __forceinline__ float maxval_of(int z) {
    switch (z) {
        case 6:  return 4.f; case 7:  return 3.f; case 8:  return 2.f;
        case 16: return 6.f; case 15: return 5.f;
        case 9: case 17: case 35: case 53: case 1: return 1.f;
        default: return 4.f;
    }
}
__device__ __forceinline__ float vdw_of(int z) {
    switch (z) {
        case 1:  return 1.2f;  case 6:  return 1.7f;  case 7:  return 1.55f;
        case 8:  return 1.52f; case 9:  return 1.47f; case 15: return 1.8f;
        case 16: return 1.8f;  case 17: return 1.75f; case 35: return 1.85f;
        case 53: return 1.98f; default: return 1.6f;
    }
}
__device__ __forceinline__ float bond_of(int a, int b) {
    if (a > b) { int t = a; a = b; b = t; }
    switch (a * 64 + b) {
        case 1*64+6:  return 1.09f; case 1*64+7:  return 1.01f; case 1*64+8:  return 0.96f;
        case 6*64+6:  return 1.54f; case 6*64+7:  return 1.47f; case 6*64+8:  return 1.43f;
        case 6*64+9:  return 1.35f; case 6*64+16: return 1.82f; case 6*64+17: return 1.77f;
        case 7*64+7:  return 1.45f; case 7*64+8:  return 1.40f; case 8*64+8:  return 1.48f;
        case 8*64+15: return 1.63f; case 16*64+16: return 2.05f;
        default: return 1.5f;
    }
}
__device__ __forceinline__ int cell_coord(float v) {
    int c = (int)floorf((v + CORG) * CINV);
    return min(max(c, 0), NCELL - 1);
}
__device__ __forceinline__ int cell_of(float x, float y, float z) {
    return (cell_coord(z) * NCELL + cell_coord(y)) * NCELL + cell_coord(x);
}

// ---------------- K1: build padded CSR of edge ids ----------------
__global__ void k_fill(const int* __restrict__ row, int E) {
    int e = blockIdx.x * blockDim.x + threadIdx.x;
    if (e < E) {
        int r = row[e];
        int p = atomicAdd(&g_cursor[r], 1);
        if (p < ROWCAP) g_csr[r * ROWCAP + p] = e;
    }
}

// -------- fast push chain: prefetch 8 neighbors, rsqrt math (validated 1.44e-7) ----
__device__ __forceinline__ void push8(float s, int m, const int* cc,
                                      const float* nx, const float* ny, const float* nz,
                                      const int* sk, float& x, float& y, float& z) {
    #pragma unroll
    for (int t = 0; t < 8; t++) {
        if (t < m && !sk[t]) {
            float dx = x - nx[t], dy = y - ny[t], dz = z - nz[t];
            float d2 = dx * dx + dy * dy + dz * dz;
            float f = s * rsqrtf(fmaxf(d2, 1e-24f));
            x += dx * f; y += dy * f; z += dz * f;
        }
    }
}

// ---------------- K2: sweep 1 (sort violating rows, viol/loss1/rad8, push) --------
__global__ void __launch_bounds__(64) k_sweep1(const float* __restrict__ orig,
                                               const int* __restrict__ col,
                                               const int* __restrict__ types, int N) {
    __shared__ float sl[64];
    int tid = threadIdx.x;
    int i = blockIdx.x * 64 + tid;
    float lloss = 0.0f;
    if (i < N) {
        int deg = g_cursor[i];
        int cnt = min(deg, ROWCAP);
        int z = types[i];
        float v = fmaxf((float)deg - maxval_of(z), 0.0f);
        g_viol[i] = v;
        lloss = v * v;
        g_rad8[i] = vdw_of(z) * 0.8f;
        float x = orig[3*i], y = orig[3*i+1], zz = orig[3*i+2];
        if (v > 0.0f) {
            int base = i * ROWCAP;
            int eid[ROWCAP];
            for (int k = 0; k < cnt; k++) eid[k] = g_csr[base + k];
            for (int a = 1; a < cnt; a++) {          // stable = ascending edge id
                int key = eid[a]; int t = a - 1;
                while (t >= 0 && eid[t] > key) { eid[t+1] = eid[t]; t--; }
                eid[t+1] = key;
            }
            float s = v * 1e-3f;
            for (int k0 = 0; k0 < cnt; k0 += 8) {
                int m = min(cnt - k0, 8);
                int cc[8]; int sk[8]; float nx[8], ny[8], nz[8];
                #pragma unroll
                for (int t = 0; t < 8; t++) {
                    if (t < m) {
                        int c = col[eid[k0 + t]];
                        cc[t] = c;
                        g_csr[base + k0 + t] = c;    // rewrite CSR with col values
                        sk[t] = (c == i);            // self-edge: exactly 0 contribution
                        nx[t] = orig[3*c]; ny[t] = orig[3*c+1]; nz[t] = orig[3*c+2];
                    } else sk[t] = 1;
                }
                push8(s, m, cc, nx, ny, nz, sk, x, y, zz);
            }
        }
        g_pA[3*i] = x; g_pA[3*i+1] = y; g_pA[3*i+2] = zz;
    }
    sl[tid] = lloss;
    for (int d = 32; d > 0; d >>= 1) {
        __syncthreads();
        if (tid < d) sl[tid] += sl[tid + d];
    }
    __syncthreads();
    if (tid == 0) g_l1part[blockIdx.x] = sl[0];
}

// ---------------- K3/K4: later sweeps (rows < i read previous sweep result) -------
__global__ void __launch_bounds__(64) k_sweepN(const float* __restrict__ orig,
                                               const float* __restrict__ prev,
                                               float* __restrict__ out,
                                               int N, int writePos2) {
    int i = blockIdx.x * 64 + threadIdx.x;
    if (i >= N) return;
    float x = orig[3*i], y = orig[3*i+1], z = orig[3*i+2];
    float v = g_viol[i];
    if (v > 0.0f) {
        int cnt = min(g_cursor[i], ROWCAP);
        float s = v * 1e-3f;
        int base = i * ROWCAP;
        for (int k0 = 0; k0 < cnt; k0 += 8) {
            int m = min(cnt - k0, 8);
            int cc[8]; int sk[8]; float nx[8], ny[8], nz[8];
            #pragma unroll
            for (int t = 0; t < 8; t++) {
                if (t < m) {
                    int c = g_csr[base + k0 + t];     // col values (sweep1 rewrote)
                    cc[t] = c;
                    sk[t] = (c == i);
                    const float* pc = (c < i) ? prev : orig;
                    nx[t] = pc[3*c]; ny[t] = pc[3*c+1]; nz[t] = pc[3*c+2];
                } else sk[t] = 1;
            }
            push8(s, m, cc, nx, ny, nz, sk, x, y, z);
        }
    }
    out[3*i] = x; out[3*i+1] = y; out[3*i+2] = z;
    if (writePos2) { g_pos2[3*i] = x; g_pos2[3*i+1] = y; g_pos2[3*i+2] = z; }
}

// ---------------- K5: fused bond correction (blocks [0,nbE)) + cell counts --------
// Cell binning uses p1 (pre-bond); bond drift <= 6e-3 is inside the cutoff margin.
__global__ void k_bondcell(const float* __restrict__ p1, const int* __restrict__ row,
                           const int* __restrict__ col, const int* __restrict__ types,
                           int E, int N, int nbE) {
    __shared__ float sl[256];
    int tid = threadIdx.x;
    if ((int)blockIdx.x < nbE) {
        int e = blockIdx.x * blockDim.x + tid;
        float l = 0.0f;
        if (e < E) {
            int r = row[e], c = col[e];
            float dx = p1[3*r]   - p1[3*c];
            float dy = p1[3*r+1] - p1[3*c+1];
            float dz = p1[3*r+2] - p1[3*c+2];
            float cur = sqrtf(dx*dx + dy*dy + dz*dz);
            float tgt = bond_of(types[r], types[c]);
            float df = cur - tgt;
            l = df * df;
            float ratio = fminf(fmaxf(tgt / (cur + 1e-8f), 0.98f), 1.02f);
            float sc = (ratio - 1.0f) * 0.005f;      // *0.01*0.5
            atomicAdd(&g_pos2[3*r],     dx * sc);
            atomicAdd(&g_pos2[3*r+1],   dy * sc);
            atomicAdd(&g_pos2[3*r+2],   dz * sc);
            atomicAdd(&g_pos2[3*c],    -dx * sc);
            atomicAdd(&g_pos2[3*c+1],  -dy * sc);
            atomicAdd(&g_pos2[3*c+2],  -dz * sc);
        }
        sl[tid] = l;
        for (int d = 128; d > 0; d >>= 1) {
            __syncthreads();
            if (tid < d) sl[tid] += sl[tid + d];
        }
        __syncthreads();
        if (tid == 0) g_l2part[blockIdx.x] = sl[0];
    } else {
        int i = (blockIdx.x - nbE) * blockDim.x + tid;
        if (i < N)
            atomicAdd(&g_ccount[cell_of(p1[3*i], p1[3*i+1], p1[3*i+2])], 1);
    }
}

// ---------------- K6: exclusive scan of cell counts (single block) ----------------
__global__ void k_cellscan(int NI) {
    __shared__ int ss[1024];
    int tid  = threadIdx.x;
    int base = tid * NI;
    int local[16];
    int s = 0;
    for (int k = 0; k < NI; k++) {
        int i = base + k;
        int c = (i < NCELL3) ? g_ccount[i] : 0;
        local[k] = s;
        s += c;
    }
    ss[tid] = s;
    __syncthreads();
    for (int d = 1; d < 1024; d <<= 1) {
        int v = (tid >= d) ? ss[tid - d] : 0;
        __syncthreads();
        ss[tid] += v;
        __syncthreads();
    }
    int excl = ss[tid] - s;
    for (int k = 0; k < NI; k++) {
        int i = base + k;
        if (i < NCELL3) g_coff[i] = excl + local[k];
    }
    if (tid == 0) g_coff[NCELL3] = ss[1023];
}

// ---------------- K7: fill cell CSR with pos2 packed ----------------
__global__ void k_cellfill(const float* __restrict__ p1, int N) {
    int i = blockIdx.x * blockDim.x + threadIdx.x;
    if (i >= N) return;
    int c = cell_of(p1[3*i], p1[3*i+1], p1[3*i+2]);  // identical binning to count
    int p = atomicAdd(&g_ccur[c], 1);
    int slot = g_coff[c] + p;
    g_catom[slot] = make_float4(g_pos2[3*i], g_pos2[3*i+1], g_pos2[3*i+2], g_rad8[i]);
    g_cidx[slot] = i;
}

// ---------------- K8: steric (warp-per-slot) + fused finalize + counter reset -----
__global__ void __launch_bounds__(256) k_steric(float* __restrict__ out, int N, int E,
                                                int nbS, int out_size) {
    __shared__ float sl[8];
    __shared__ float sh[256];
    __shared__ int   amLast;
    int tid  = threadIdx.x;
    int lane = tid & 31;
    int wid  = tid >> 5;
    int s = blockIdx.x * 8 + wid;                // slot (cell-ordered)
    float loss = 0.0f;
    if (s < N) {
        float4 me = g_catom[s];
        int i = g_cidx[s];
        int cx = cell_coord(me.x), cy = cell_coord(me.y), cz = cell_coord(me.z);
        int xlo = max(cx - 1, 0), xhi = min(cx + 1, NCELL - 1);
        int ylo = max(cy - 1, 0), yhi = min(cy + 1, NCELL - 1);
        int zlo = max(cz - 1, 0), zhi = min(cz + 1, NCELL - 1);
        float csum = 0.0f, cvx = 0.0f, cvy = 0.0f, cvz = 0.0f;
        for (int z = zlo; z <= zhi; z++)
            for (int y = ylo; y <= yhi; y++) {
                int rowc = (z * NCELL + y) * NCELL;
                int kb = g_coff[rowc + xlo];
                int ke = g_coff[rowc + xhi + 1];  // x-neighbors are contiguous cells
                for (int k = kb + lane; k < ke; k += 32) {
                    float4 q = g_catom[k];
                    if (k == s) continue;         // exactly the i==j diagonal
                    float dx = me.x - q.x, dy = me.y - q.y, dz = me.z - q.z;
                    float d2 = dx*dx + dy*dy + dz*dz;
                    float mind = me.w + q.w;
                    if (d2 < mind * mind) {
                        float d2c = fmaxf(d2, 1e-20f);
                        float inv = rsqrtf(d2c);
                        float dist = d2c * inv;
                        float tt = mind - dist;
                        if (tt > 0.0f) {
                            loss += tt * tt;
                            if (dist > 1e-8f) {
                                float cc = tt * 0.0025f * inv;   // (mind-d)*0.005*0.5/d
                                csum += cc;
                                cvx += cc * q.x; cvy += cc * q.y; cvz += cc * q.z;
                            }
                        }
                    }
                }
            }
        #pragma unroll
        for (int d = 16; d > 0; d >>= 1) {
            csum += __shfl_xor_sync(0xffffffff, csum, d);
            cvx  += __shfl_xor_sync(0xffffffff, cvx,  d);
            cvy  += __shfl_xor_sync(0xffffffff, cvy,  d);
            cvz  += __shfl_xor_sync(0xffffffff, cvz,  d);
            loss += __shfl_xor_sync(0xffffffff, loss, d);
        }
        if (lane == 0) {
            out[3*i]   = me.x + csum * me.x - cvx;
            out[3*i+1] = me.y + csum * me.y - cvy;
            out[3*i+2] = me.z + csum * me.z - cvz;
        }
    }
    if (lane == 0) sl[wid] = loss;
    // reset counters for next replay (their last readers ran in earlier launches)
    {
        int gs = gridDim.x * blockDim.x;
        int gt = blockIdx.x * blockDim.x + tid;
        for (int k = gt; k < N_MAX;  k += gs) g_cursor[k] = 0;
        for (int k = gt; k < NCELL3; k += gs) { g_ccount[k] = 0; g_ccur[k] = 0; }
    }
    __syncthreads();
    if (tid == 0) {
        float t = 0.0f;
        #pragma unroll
        for (int w = 0; w < 8; w++) t += sl[w];
        g_l3part[blockIdx.x] = t;
        __threadfence();
        amLast = (atomicAdd(&g_done, 1) == nbS - 1);
    }
    __syncthreads();
    // ---- last block: finalize loss (deterministic fixed-order sums) ----
    if (amLast) {
        float a = 0.0f;
        for (int k = tid; k < 128; k += 256)
            a += __ldcg(&g_l1part[k]) + __ldcg(&g_l2part[k]) / (float)E;
        for (int k = tid; k < nbS; k += 256)
            a += 0.5f * __ldcg(&g_l3part[k]);
        sh[tid] = a;
        for (int d = 128; d > 0; d >>= 1) {
            __syncthreads();
            if (tid < d) sh[tid] += sh[tid + d];
        }
        __syncthreads();
        if (tid == 0) { out[3*N] = sh[0] * 0.1f; g_done = 0; }
        for (int k = 3*N + 1 + tid; k < out_size; k += 256) out[k] = 0.0f;
    }
}

// ---------------- launcher: 8 kernels ----------------
extern "C" void kernel_launch(void* const* d_in, const int* in_sizes, int n_in,
                              void* d_out, int out_size) {
    const float* pos   = (const float*)d_in[0];
    const int*   edge  = (const int*)d_in[1];
    const int*   types = (const int*)d_in[2];
    float*       out   = (float*)d_out;

    int N = in_sizes[0] / 3;
    int E = in_sizes[1] / 2;
    const int* row = edge;
    const int* col = edge + E;

    int nbE  = (E + 255) / 256;           // 128
    int nb64 = (N + 63) / 64;             // 128
    int nbN  = (N + 255) / 256;           // 32
    int NIc  = (NCELL3 + 1023) / 1024;    // 16
    int nbS  = (N + 7) / 8;               // 1024 (warp per slot)

    k_fill<<<nbE, 256>>>(row, E);
    k_sweep1<<<nb64, 64>>>(pos, col, types, N);
    // 3 Jacobi sweeps converge to the exact sequential scan (2 sweeps measured
    // insufficient in R6: 1.4e-3; 3 sweeps: ~1.4e-7).
    k_sweepN<<<nb64, 64>>>(pos, g_pA, g_pB, N, 0);
    k_sweepN<<<nb64, 64>>>(pos, g_pB, g_pA, N, 1);   // seeds g_pos2
    k_bondcell<<<nbE + nbN, 256>>>(g_pA, row, col, types, E, N, nbE);
    k_cellscan<<<1, 1024>>>(NIc);
    k_cellfill<<<nbN, 256>>>(g_pA, N);
    k_steric<<<nbS, 256>>>(out, N, E, nbS, out_size);
}

// round 15
// speedup vs baseline: 1.7527x; 1.0770x over previous
#include <cuda_runtime.h>
#include <math.h>

// Fixed problem shapes: N=8192 atoms, E=32768 edges (guarded for safety).
#define N_MAX   8192
#define E_MAX   32768
#define ROWCAP  32          // padded CSR row capacity; one row == one 128B cache line
#define NCELL   25
#define NCELL3  15625       // 25^3
#define CINV    0.3125f     // 1/3.2 ; cell 3.2 > max cutoff 3.168 + drift margin
#define CORG    40.0f
#define SPIN_LIMIT 200000000u  // bounded spin -> deadlock becomes fast wrong-result
#define ABLK    128
#define ATHR    64
#define BBLK    160         // 128 bond-blocks + 32 cellcount-blocks
#define BTHR    256

// ---------------- device scratch (zero-init; restored each run by KC) -------------
__device__ int    g_cursor[N_MAX];
__device__ int    g_csr[N_MAX * ROWCAP];    // edge ids; after sweep1 (violating rows): cols
__device__ float  g_viol[N_MAX];
__device__ float  g_rad8[N_MAX];
__device__ float  g_pA[N_MAX * 3];
__device__ float  g_pB[N_MAX * 3];
__device__ float  g_pos2[N_MAX * 3];
__device__ int    g_ccount[NCELL3];
__device__ int    g_ccur[NCELL3];
__device__ int    g_coff[NCELL3 + 1];
__device__ float4 g_catom[N_MAX];
__device__ int    g_cidx[N_MAX];
__device__ float  g_l1part[ABLK];
__device__ float  g_l2part[ABLK];
__device__ float  g_l3part[1024];
__device__ int    g_barc[8];                // spin-barrier counters (KA:0-2, KB:3-4)
__device__ int    g_done;                   // KC last-block ticket

// ---------------- chemistry as branchy constants ----------------
__device__ __forceinline__ float maxval_of(int z) {
    switch (z) {
        case 6:  return 4.f; case 7:  return 3.f; case 8:  return 2.f;
        case 16: return 6.f; case 15: return 5.f;
        case 9: case 17: case 35: case 53: case 1: return 1.f;
        default: return 4.f;
    }
}
__device__ __forceinline__ float vdw_of(int z) {
    switch (z) {
        case 1:  return 1.2f;  case 6:  return 1.7f;  case 7:  return 1.55f;
        case 8:  return 1.52f; case 9:  return 1.47f; case 15: return 1.8f;
        case 16: return 1.8f;  case 17: return 1.75f; case 35: return 1.85f;
        case 53: return 1.98f; default: return 1.6f;
    }
}
__device__ __forceinline__ float bond_of(int a, int b) {
    if (a > b) { int t = a; a = b; b = t; }
    switch (a * 64 + b) {
        case 1*64+6:  return 1.09f; case 1*64+7:  return 1.01f; case 1*64+8:  return 0.96f;
        case 6*64+6:  return 1.54f; case 6*64+7:  return 1.47f; case 6*64+8:  return 1.43f;
        case 6*64+9:  return 1.35f; case 6*64+16: return 1.82f; case 6*64+17: return 1.77f;
        case 7*64+7:  return 1.45f; case 7*64+8:  return 1.40f; case 8*64+8:  return 1.48f;
        case 8*64+15: return 1.63f; case 16*64+16: return 2.05f;
        default: return 1.5f;
    }
}
__device__ __forceinline__ int cell_coord(float v) {
    int c = (int)floorf((v + CORG) * CINV);
    return min(max(c, 0), NCELL - 1);
}
__device__ __forceinline__ int cell_of(float x, float y, float z) {
    return (cell_coord(z) * NCELL + cell_coord(y)) * NCELL + cell_coord(x);
}

// ------ grid-wide bounded spin barrier (all blocks of the launching grid resident) --
__device__ __forceinline__ void gbar(int idx, int nblk) {
    __syncthreads();
    if (threadIdx.x == 0) {
        __threadfence();
        atomicAdd(&g_barc[idx], 1);
        unsigned spins = 0;
        while (*(volatile int*)&g_barc[idx] < nblk) {
            if (++spins > SPIN_LIMIT) break;   // fail-open diagnostic; never trips normally
            __nanosleep(32);
        }
        __threadfence();
    }
    __syncthreads();
}

// -------- fast push chain: prefetch 8 neighbors, rsqrt math (validated 2.3e-7) ------
__device__ __forceinline__ void push8(float s, int m,
                                      const float* nx, const float* ny, const float* nz,
                                      const int* sk, float& x, float& y, float& z) {
    #pragma unroll
    for (int t = 0; t < 8; t++) {
        if (t < m && !sk[t]) {
            float dx = x - nx[t], dy = y - ny[t], dz = z - nz[t];
            float d2 = dx * dx + dy * dy + dz * dz;
            float f = s * rsqrtf(fmaxf(d2, 1e-24f));
            x += dx * f; y += dy * f; z += dz * f;
        }
    }
}

// ================= KA: fill + 3 Jacobi sweeps (128 x 64, 3 grid barriers) ==========
__global__ void __launch_bounds__(ATHR) kA(const float* __restrict__ orig,
                                           const int* __restrict__ row,
                                           const int* __restrict__ col,
                                           const int* __restrict__ types,
                                           int N, int E) {
    __shared__ float sl[ATHR];
    const int tid  = threadIdx.x;
    const int bid  = blockIdx.x;
    const int gtid = bid * ATHR + tid;          // == atom id in sweep phases
    const int GT   = ABLK * ATHR;               // 8192

    // ---- fill: padded CSR of edge ids (slot order irrelevant; sweep1 sorts) ----
    for (int e = gtid; e < E; e += GT) {
        int r = row[e];
        int p = atomicAdd(&g_cursor[r], 1);
        if (p < ROWCAP) g_csr[r * ROWCAP + p] = e;
    }
    gbar(0, ABLK);

    // ---- sweep 1: sort violating rows, viol/loss1/rad8, push ----
    {
        float lloss = 0.0f;
        int i = gtid;
        if (i < N) {
            int deg = __ldcg(&g_cursor[i]);      // written by other blocks' atomics
            int cnt = min(deg, ROWCAP);
            int z = types[i];
            float v = fmaxf((float)deg - maxval_of(z), 0.0f);
            g_viol[i] = v;
            lloss = v * v;
            g_rad8[i] = vdw_of(z) * 0.8f;
            float x = orig[3*i], y = orig[3*i+1], zz = orig[3*i+2];
            if (v > 0.0f) {
                int base = i * ROWCAP;
                int eid[ROWCAP];
                for (int k = 0; k < cnt; k++) eid[k] = __ldcg(&g_csr[base + k]);
                for (int a = 1; a < cnt; a++) {  // stable = ascending edge id
                    int key = eid[a]; int t = a - 1;
                    while (t >= 0 && eid[t] > key) { eid[t+1] = eid[t]; t--; }
                    eid[t+1] = key;
                }
                float s = v * 1e-3f;
                for (int k0 = 0; k0 < cnt; k0 += 8) {
                    int m = min(cnt - k0, 8);
                    int sk[8]; float nx[8], ny[8], nz[8];
                    #pragma unroll
                    for (int t = 0; t < 8; t++) {
                        if (t < m) {
                            int c = col[eid[k0 + t]];
                            g_csr[base + k0 + t] = c;   // rewrite own row (one line) with cols
                            sk[t] = (c == i);           // self-edge: exactly 0 contribution
                            nx[t] = orig[3*c]; ny[t] = orig[3*c+1]; nz[t] = orig[3*c+2];
                        } else sk[t] = 1;
                    }
                    push8(s, m, nx, ny, nz, sk, x, y, zz);
                }
            }
            g_pA[3*i] = x; g_pA[3*i+1] = y; g_pA[3*i+2] = zz;
        }
        sl[tid] = lloss;
        for (int d = ATHR/2; d > 0; d >>= 1) {
            __syncthreads();
            if (tid < d) sl[tid] += sl[tid + d];
        }
        __syncthreads();
        if (tid == 0) g_l1part[bid] = sl[0];
    }
    gbar(1, ABLK);

    // ---- sweeps 2 & 3 (rows < i read previous sweep's result; first-touch lines) ----
    #pragma unroll 1
    for (int sweep = 0; sweep < 2; sweep++) {
        const float* prev = (sweep == 0) ? g_pA : g_pB;
        float* outp       = (sweep == 0) ? g_pB : g_pA;
        int i = gtid;
        if (i < N) {
            float x = orig[3*i], y = orig[3*i+1], zz = orig[3*i+2];
            float v = g_viol[i];                 // own thread wrote it
            if (v > 0.0f) {
                int cnt = min(__ldcg(&g_cursor[i]), ROWCAP);
                float s = v * 1e-3f;
                int base = i * ROWCAP;
                for (int k0 = 0; k0 < cnt; k0 += 8) {
                    int m = min(cnt - k0, 8);
                    int sk[8]; float nx[8], ny[8], nz[8];
                    #pragma unroll
                    for (int t = 0; t < 8; t++) {
                        if (t < m) {
                            int c = g_csr[base + k0 + t];  // own row, own thread rewrote it
                            sk[t] = (c == i);
                            const float* pc = (c < i) ? prev : orig;
                            nx[t] = pc[3*c]; ny[t] = pc[3*c+1]; nz[t] = pc[3*c+2];
                        } else sk[t] = 1;
                    }
                    push8(s, m, nx, ny, nz, sk, x, y, zz);
                }
            }
            outp[3*i] = x; outp[3*i+1] = y; outp[3*i+2] = zz;
            if (sweep == 1) { g_pos2[3*i] = x; g_pos2[3*i+1] = y; g_pos2[3*i+2] = zz; }
        }
        if (sweep == 0) gbar(2, ABLK);
    }
}

// ===== KB: bond+cellcount | scan | cellfill (160 x 256, 2 grid barriers) ===========
__global__ void __launch_bounds__(BTHR) kB(const float* __restrict__ row_f_unused,
                                           const int* __restrict__ row,
                                           const int* __restrict__ col,
                                           const int* __restrict__ types,
                                           int N, int E) {
    __shared__ float sl[BTHR];
    __shared__ int   shi[BTHR];
    const int tid = threadIdx.x;
    const int bid = blockIdx.x;

    // ---- bond correction (blocks 0..127) + cell counts (blocks 128..159) ----
    if (bid < ABLK) {
        int e = bid * BTHR + tid;               // 128*256 = 32768 = E
        float l = 0.0f;
        if (e < E) {
            int r = row[e], c = col[e];
            float dx = g_pA[3*r]   - g_pA[3*c];
            float dy = g_pA[3*r+1] - g_pA[3*c+1];
            float dz = g_pA[3*r+2] - g_pA[3*c+2];
            float cur = sqrtf(dx*dx + dy*dy + dz*dz);
            float tgt = bond_of(types[r], types[c]);
            float df = cur - tgt;
            l = df * df;
            float ratio = fminf(fmaxf(tgt / (cur + 1e-8f), 0.98f), 1.02f);
            float sc = (ratio - 1.0f) * 0.005f;  // *0.01*0.5
            atomicAdd(&g_pos2[3*r],     dx * sc);
            atomicAdd(&g_pos2[3*r+1],   dy * sc);
            atomicAdd(&g_pos2[3*r+2],   dz * sc);
            atomicAdd(&g_pos2[3*c],    -dx * sc);
            atomicAdd(&g_pos2[3*c+1],  -dy * sc);
            atomicAdd(&g_pos2[3*c+2],  -dz * sc);
        }
        sl[tid] = l;
        for (int d = BTHR/2; d > 0; d >>= 1) {
            __syncthreads();
            if (tid < d) sl[tid] += sl[tid + d];
        }
        __syncthreads();
        if (tid == 0) g_l2part[bid] = sl[0];
    } else {
        int i = (bid - ABLK) * BTHR + tid;      // 32*256 = 8192 = N
        if (i < N)
            atomicAdd(&g_ccount[cell_of(g_pA[3*i], g_pA[3*i+1], g_pA[3*i+2])], 1);
    }
    gbar(3, BBLK);

    // ---- exclusive scan of cell counts (block 0, two-pass: no big local array) ----
    if (bid == 0) {
        const int NI = (NCELL3 + BTHR - 1) / BTHR;   // 62
        int s = 0;
        for (int k = 0; k < NI; k++) {
            int idx = tid * NI + k;
            if (idx < NCELL3) s += __ldcg(&g_ccount[idx]);
        }
        shi[tid] = s;
        __syncthreads();
        for (int d = 1; d < BTHR; d <<= 1) {
            int v = (tid >= d) ? shi[tid - d] : 0;
            __syncthreads();
            shi[tid] += v;
            __syncthreads();
        }
        int run = shi[tid] - s;
        for (int k = 0; k < NI; k++) {
            int idx = tid * NI + k;
            if (idx < NCELL3) { g_coff[idx] = run; run += __ldcg(&g_ccount[idx]); }
        }
        if (tid == 0) g_coff[NCELL3] = shi[BTHR - 1];
    }
    gbar(4, BBLK);

    // ---- cell fill (first 32 blocks; first-touch reads of pos2/g_coff) ----
    if (bid < 32) {
        int i = bid * BTHR + tid;
        if (i < N) {
            int c = cell_of(g_pA[3*i], g_pA[3*i+1], g_pA[3*i+2]);  // identical binning
            int p = atomicAdd(&g_ccur[c], 1);
            int slot = __ldcg(&g_coff[c]) + p;
            g_catom[slot] = make_float4(__ldcg(&g_pos2[3*i]), __ldcg(&g_pos2[3*i+1]),
                                        __ldcg(&g_pos2[3*i+2]), g_rad8[i]);
            g_cidx[slot] = i;
        }
    }
}

// ===== KC: steric (warp-per-slot) + fused finalize + all resets ====================
__global__ void __launch_bounds__(256) kC(float* __restrict__ out, int N, int E,
                                          int nbS, int out_size) {
    __shared__ float sl[8];
    __shared__ float sh[256];
    __shared__ int   amLast;
    int tid  = threadIdx.x;
    int lane = tid & 31;
    int wid  = tid >> 5;
    int s = blockIdx.x * 8 + wid;               // slot (cell-ordered)
    float loss = 0.0f;
    if (s < N) {
        float4 me = g_catom[s];
        int i = g_cidx[s];
        int cx = cell_coord(me.x), cy = cell_coord(me.y), cz = cell_coord(me.z);
        int xlo = max(cx - 1, 0), xhi = min(cx + 1, NCELL - 1);
        int ylo = max(cy - 1, 0), yhi = min(cy + 1, NCELL - 1);
        int zlo = max(cz - 1, 0), zhi = min(cz + 1, NCELL - 1);
        float csum = 0.0f, cvx = 0.0f, cvy = 0.0f, cvz = 0.0f;
        for (int z = zlo; z <= zhi; z++)
            for (int y = ylo; y <= yhi; y++) {
                int rowc = (z * NCELL + y) * NCELL;
                int kb = g_coff[rowc + xlo];
                int ke = g_coff[rowc + xhi + 1]; // x-neighbors are contiguous cells
                for (int k = kb + lane; k < ke; k += 32) {
                    float4 q = g_catom[k];
                    if (k == s) continue;        // exactly the i==j diagonal
                    float dx = me.x - q.x, dy = me.y - q.y, dz = me.z - q.z;
                    float d2 = dx*dx + dy*dy + dz*dz;
                    float mind = me.w + q.w;
                    if (d2 < mind * mind) {
                        float d2c = fmaxf(d2, 1e-20f);
                        float inv = rsqrtf(d2c);
                        float dist = d2c * inv;
                        float tt = mind - dist;
                        if (tt > 0.0f) {
                            loss += tt * tt;
                            if (dist > 1e-8f) {
                                float cc = tt * 0.0025f * inv;  // (mind-d)*0.005*0.5/d
                                csum += cc;
                                cvx += cc * q.x; cvy += cc * q.y; cvz += cc * q.z;
                            }
                        }
                    }
                }
            }
        #pragma unroll
        for (int d = 16; d > 0; d >>= 1) {
            csum += __shfl_xor_sync(0xffffffff, csum, d);
            cvx  += __shfl_xor_sync(0xffffffff, cvx,  d);
            cvy  += __shfl_xor_sync(0xffffffff, cvy,  d);
            cvz  += __shfl_xor_sync(0xffffffff, cvz,  d);
            loss += __shfl_xor_sync(0xffffffff, loss, d);
        }
        if (lane == 0) {
            out[3*i]   = me.x + csum * me.x - cvx;
            out[3*i+1] = me.y + csum * me.y - cvy;
            out[3*i+2] = me.z + csum * me.z - cvz;
        }
    }
    if (lane == 0) sl[wid] = loss;
    // reset all scratch counters + barriers for the next graph replay
    {
        int gs = gridDim.x * blockDim.x;
        int gt = blockIdx.x * blockDim.x + tid;
        for (int k = gt; k < N_MAX;  k += gs) g_cursor[k] = 0;
        for (int k = gt; k < NCELL3; k += gs) { g_ccount[k] = 0; g_ccur[k] = 0; }
        if (gt < 8) g_barc[gt] = 0;
    }
    __syncthreads();
    if (tid == 0) {
        float t = 0.0f;
        #pragma unroll
        for (int w = 0; w < 8; w++) t += sl[w];
        g_l3part[blockIdx.x] = t;
        __threadfence();
        amLast = (atomicAdd(&g_done, 1) == nbS - 1);
    }
    __syncthreads();
    // ---- last block: finalize loss (deterministic fixed-order sums) ----
    if (amLast) {
        float a = 0.0f;
        for (int k = tid; k < ABLK; k += 256)
            a += __ldcg(&g_l1part[k]) + __ldcg(&g_l2part[k]) / (float)E;
        for (int k = tid; k < nbS; k += 256)
            a += 0.5f * __ldcg(&g_l3part[k]);
        sh[tid] = a;
        for (int d = 128; d > 0; d >>= 1) {
            __syncthreads();
            if (tid < d) sh[tid] += sh[tid + d];
        }
        __syncthreads();
        if (tid == 0) { out[3*N] = sh[0] * 0.1f; g_done = 0; }
        for (int k = 3*N + 1 + tid; k < out_size; k += 256) out[k] = 0.0f;
    }
}

// ---------------- launcher: 3 kernels ----------------
extern "C" void kernel_launch(void* const* d_in, const int* in_sizes, int n_in,
                              void* d_out, int out_size) {
    const float* pos   = (const float*)d_in[0];
    const int*   edge  = (const int*)d_in[1];
    const int*   types = (const int*)d_in[2];
    float*       out   = (float*)d_out;

    int N = in_sizes[0] / 3;
    int E = in_sizes[1] / 2;
    const int* row = edge;
    const int* col = edge + E;

    int nbS = (N + 7) / 8;                  // 1024 steric blocks (warp per slot)

    kA<<<ABLK, ATHR>>>(pos, row, col, types, N, E);
    kB<<<BBLK, BTHR>>>(pos, row, col, types, N, E);
    kC<<<nbS, 256>>>(out, N, E, nbS, out_size);
}